// round 4
// baseline (speedup 1.0000x reference)
#include <cuda_runtime.h>
#include <cstdint>

// Problem constants
#define TOK   8192      // b*n tokens
#define EMB_  768
#define NQKV  2304
#define HEADS_ 8
#define HDIM  96
#define SEQ   2048
#define BATCH 4

// ---------------- scratch (static device globals; no runtime allocation) ----
__device__ float g_y[TOK * NQKV];                       // qkv pre-act  (75.5MB)
__device__ float g_q[BATCH * HEADS_ * SEQ * HDIM];      // 25.2MB
__device__ float g_k[BATCH * HEADS_ * SEQ * HDIM];
__device__ float g_v[BATCH * HEADS_ * SEQ * HDIM];
__device__ float g_ctx[TOK * EMB_];                     // attention out (b,n,e)

// ---------------- helpers ---------------------------------------------------
__device__ __forceinline__ float tf32r(float x) {
    unsigned u;
    asm("cvt.rna.tf32.f32 %0, %1;" : "=r"(u) : "f"(x));
    return __uint_as_float(u);
}

// D += A(16x8,row) * B(8x8,col), tf32 in / f32 acc
__device__ __forceinline__ void mma8(float c[4], const unsigned a[4], const unsigned b[2]) {
    asm volatile(
        "mma.sync.aligned.m16n8k8.row.col.f32.tf32.tf32.f32 "
        "{%0,%1,%2,%3}, {%4,%5,%6,%7}, {%8,%9}, {%0,%1,%2,%3};"
        : "+f"(c[0]), "+f"(c[1]), "+f"(c[2]), "+f"(c[3])
        : "r"(a[0]), "r"(a[1]), "r"(a[2]), "r"(a[3]), "r"(b[0]), "r"(b[1]));
}

// ---------------- generic tf32 GEMM: C = A[MxK] @ W[KxN] + bias -------------
#define BM  128
#define BN  128
#define BKT 32
#define LDA 36      // smem A stride (36 % 32 == 4 -> conflict-free A frags)
#define LDB 136     // smem B stride (136 % 32 == 8 -> conflict-free B frags)

__global__ __launch_bounds__(256, 1) void gemm_tf32(
    const float* __restrict__ A, const float* __restrict__ W,
    const float* __restrict__ bias, float* __restrict__ C,
    int M, int N, int K)
{
    extern __shared__ float sm[];
    float* sA = sm;                   // [2][BM*LDA]
    float* sB = sm + 2 * BM * LDA;    // [2][BKT*LDB]

    const int bm = blockIdx.y * BM, bn = blockIdx.x * BN;
    const int tid = threadIdx.x;
    const int w = tid >> 5, lane = tid & 31, lq = lane >> 2, lr = lane & 3;
    const int wm = (w & 3) * 32, wn = (w >> 2) * 64;

    float acc[2][8][4];
#pragma unroll
    for (int i = 0; i < 2; i++)
#pragma unroll
        for (int j = 0; j < 8; j++)
#pragma unroll
            for (int q = 0; q < 4; q++) acc[i][j][q] = 0.f;

    const int arow = tid >> 3, ac4 = tid & 7;    // A tile: 128 rows x 8 float4
    const int brow = tid >> 5, bc4 = tid & 31;   // B tile: 32 rows x 32 float4

    // prologue: stage k-tile 0
    {
#pragma unroll
        for (int i = 0; i < 4; i++) {
            float4 v = *(const float4*)(A + (size_t)(bm + arow + 32 * i) * K + ac4 * 4);
            v.x = tf32r(v.x); v.y = tf32r(v.y); v.z = tf32r(v.z); v.w = tf32r(v.w);
            *(float4*)(sA + (arow + 32 * i) * LDA + ac4 * 4) = v;
        }
#pragma unroll
        for (int i = 0; i < 4; i++) {
            float4 v = *(const float4*)(W + (size_t)(brow + 8 * i) * N + bn + bc4 * 4);
            v.x = tf32r(v.x); v.y = tf32r(v.y); v.z = tf32r(v.z); v.w = tf32r(v.w);
            *(float4*)(sB + (brow + 8 * i) * LDB + bc4 * 4) = v;
        }
    }
    __syncthreads();

    const int nkt = K / BKT;
    for (int kt = 0; kt < nkt; ++kt) {
        float* cA = sA + (kt & 1) * (BM * LDA);
        float* cB = sB + (kt & 1) * (BKT * LDB);

        float4 ra[4], rb[4];
        if (kt + 1 < nkt) {
            int k0 = (kt + 1) * BKT;
#pragma unroll
            for (int i = 0; i < 4; i++)
                ra[i] = *(const float4*)(A + (size_t)(bm + arow + 32 * i) * K + k0 + ac4 * 4);
#pragma unroll
            for (int i = 0; i < 4; i++)
                rb[i] = *(const float4*)(W + (size_t)(k0 + brow + 8 * i) * N + bn + bc4 * 4);
        }

#pragma unroll
        for (int kk = 0; kk < 4; kk++) {
            const int k8 = kk * 8;
            unsigned af[2][4];
#pragma unroll
            for (int mi = 0; mi < 2; mi++) {
                int r = wm + mi * 16;
                af[mi][0] = __float_as_uint(cA[(r + lq) * LDA + k8 + lr]);
                af[mi][1] = __float_as_uint(cA[(r + 8 + lq) * LDA + k8 + lr]);
                af[mi][2] = __float_as_uint(cA[(r + lq) * LDA + k8 + lr + 4]);
                af[mi][3] = __float_as_uint(cA[(r + 8 + lq) * LDA + k8 + lr + 4]);
            }
            unsigned bf[8][2];
#pragma unroll
            for (int ni = 0; ni < 8; ni++) {
                int c = wn + ni * 8 + lq;
                bf[ni][0] = __float_as_uint(cB[(k8 + lr) * LDB + c]);
                bf[ni][1] = __float_as_uint(cB[(k8 + lr + 4) * LDB + c]);
            }
#pragma unroll
            for (int mi = 0; mi < 2; mi++)
#pragma unroll
                for (int ni = 0; ni < 8; ni++)
                    mma8(acc[mi][ni], af[mi], bf[ni]);
        }

        if (kt + 1 < nkt) {
            float* nA = sA + ((kt + 1) & 1) * (BM * LDA);
            float* nB = sB + ((kt + 1) & 1) * (BKT * LDB);
#pragma unroll
            for (int i = 0; i < 4; i++) {
                float4 v = ra[i];
                v.x = tf32r(v.x); v.y = tf32r(v.y); v.z = tf32r(v.z); v.w = tf32r(v.w);
                *(float4*)(nA + (arow + 32 * i) * LDA + ac4 * 4) = v;
            }
#pragma unroll
            for (int i = 0; i < 4; i++) {
                float4 v = rb[i];
                v.x = tf32r(v.x); v.y = tf32r(v.y); v.z = tf32r(v.z); v.w = tf32r(v.w);
                *(float4*)(nB + (brow + 8 * i) * LDB + bc4 * 4) = v;
            }
        }
        __syncthreads();
    }

    // epilogue: + bias, float2 stores
#pragma unroll
    for (int ni = 0; ni < 8; ni++) {
        int col = bn + wn + ni * 8 + 2 * lr;
        float b0 = bias[col], b1 = bias[col + 1];
#pragma unroll
        for (int mi = 0; mi < 2; mi++) {
            int r0 = bm + wm + mi * 16 + lq;
            float2 v0 = make_float2(acc[mi][ni][0] + b0, acc[mi][ni][1] + b1);
            float2 v1 = make_float2(acc[mi][ni][2] + b0, acc[mi][ni][3] + b1);
            *(float2*)(C + (size_t)r0 * N + col) = v0;
            *(float2*)(C + (size_t)(r0 + 8) * N + col) = v1;
        }
    }
}

// ---------------- reshape y[t, (h d 3)] -> q/k/v [b,h,n,d]; q pre-scaled ----
__global__ void reshape_qkv() {
    int gid = blockIdx.x * 256 + threadIdx.x;
    if (gid >= TOK * EMB_) return;
    int t = gid / EMB_, hd = gid - t * EMB_;
    int b = t >> 11, nn = t & 2047;
    int h = hd / HDIM, dd = hd - h * HDIM;
    const float* src = g_y + (size_t)t * NQKV + hd * 3;
    int dst = ((b * HEADS_ + h) * SEQ + nn) * HDIM + dd;
    g_q[dst] = src[0] * 0.03608439182435161f;  // 1/sqrt(768)
    g_k[dst] = src[1];
    g_v[dst] = src[2];
}

// ---------------- attention: per (b,h,128-q-rows); sum-only softmax ---------
#define AQ  128
#define AK  64
#define LQS 100   // 100 % 32 == 4 -> conflict-free A frags
#define LKS 100   // K used as B with n fast over rows: (4*lq + lr) unique
#define LVS 104   // 104 % 32 == 8 -> conflict-free B frags
#define LPS 68    // 68 % 32 == 4  -> conflict-free A frags

__global__ __launch_bounds__(256, 1) void attn_kernel() {
    extern __shared__ float sm[];
    float* sQ = sm;                     // AQ*LQS
    float* sK = sQ + AQ * LQS;          // AK*LKS
    float* sV = sK + AK * LKS;          // AK*LVS
    float* sP = sV + AK * LVS;          // AQ*LPS
    float* sL = sP + AQ * LPS;          // AQ

    const int bh = blockIdx.y;          // b*8 + h
    const int qb = blockIdx.x * AQ;
    const int tid = threadIdx.x, w = tid >> 5, lane = tid & 31;
    const int lq = lane >> 2, lr = lane & 3;
    const int wm = (w & 3) * 32, wn2 = (w >> 2);   // 4 m-warps x 2 n-warps

    const float* Qg = g_q + ((size_t)bh * SEQ + qb) * HDIM;
    const float* Kg = g_k + (size_t)bh * SEQ * HDIM;
    const float* Vg = g_v + (size_t)bh * SEQ * HDIM;

    if (tid < AQ) sL[tid] = 0.f;

    // load Q tile (tf32-rounded)
#pragma unroll
    for (int i = 0; i < 12; i++) {
        int id = tid + 256 * i;
        int r = id / 24, c4 = id - r * 24;
        float4 v = *(const float4*)(Qg + r * HDIM + c4 * 4);
        v.x = tf32r(v.x); v.y = tf32r(v.y); v.z = tf32r(v.z); v.w = tf32r(v.w);
        *(float4*)(sQ + r * LQS + c4 * 4) = v;
    }
    __syncthreads();

    float o[2][6][4];
#pragma unroll
    for (int i = 0; i < 2; i++)
#pragma unroll
        for (int j = 0; j < 6; j++)
#pragma unroll
            for (int q = 0; q < 4; q++) o[i][j][q] = 0.f;

    for (int it = 0; it < SEQ / AK; ++it) {
        const float* Kt = Kg + (size_t)it * AK * HDIM;
        const float* Vt = Vg + (size_t)it * AK * HDIM;
#pragma unroll
        for (int i = 0; i < 6; i++) {
            int id = tid + 256 * i;
            int r = id / 24, c4 = id - r * 24;
            float4 kv = *(const float4*)(Kt + r * HDIM + c4 * 4);
            kv.x = tf32r(kv.x); kv.y = tf32r(kv.y); kv.z = tf32r(kv.z); kv.w = tf32r(kv.w);
            *(float4*)(sK + r * LKS + c4 * 4) = kv;
            float4 vv = *(const float4*)(Vt + r * HDIM + c4 * 4);
            vv.x = tf32r(vv.x); vv.y = tf32r(vv.y); vv.z = tf32r(vv.z); vv.w = tf32r(vv.w);
            *(float4*)(sV + r * LVS + c4 * 4) = vv;
        }
        __syncthreads();

        // S[128x64] = Q @ K^T  (warp tile 32x32)
        float s[2][4][4];
#pragma unroll
        for (int i = 0; i < 2; i++)
#pragma unroll
            for (int j = 0; j < 4; j++)
#pragma unroll
                for (int q = 0; q < 4; q++) s[i][j][q] = 0.f;

#pragma unroll
        for (int kk = 0; kk < 12; kk++) {
            int k8 = kk * 8;
            unsigned af[2][4];
#pragma unroll
            for (int mi = 0; mi < 2; mi++) {
                int r = wm + mi * 16;
                af[mi][0] = __float_as_uint(sQ[(r + lq) * LQS + k8 + lr]);
                af[mi][1] = __float_as_uint(sQ[(r + 8 + lq) * LQS + k8 + lr]);
                af[mi][2] = __float_as_uint(sQ[(r + lq) * LQS + k8 + lr + 4]);
                af[mi][3] = __float_as_uint(sQ[(r + 8 + lq) * LQS + k8 + lr + 4]);
            }
            unsigned bf[4][2];
#pragma unroll
            for (int ni = 0; ni < 4; ni++) {
                int c = wn2 * 32 + ni * 8 + lq;
                bf[ni][0] = __float_as_uint(sK[c * LKS + k8 + lr]);
                bf[ni][1] = __float_as_uint(sK[c * LKS + k8 + lr + 4]);
            }
#pragma unroll
            for (int mi = 0; mi < 2; mi++)
#pragma unroll
                for (int ni = 0; ni < 4; ni++)
                    mma8(s[mi][ni], af[mi], bf[ni]);
        }

        // exp -> P (tf32-rounded; same values feed row sums for consistency)
        float rs[2][2] = {{0.f, 0.f}, {0.f, 0.f}};
#pragma unroll
        for (int mi = 0; mi < 2; mi++) {
            int r0 = wm + mi * 16 + lq;
#pragma unroll
            for (int ni = 0; ni < 4; ni++) {
                int col = wn2 * 32 + ni * 8 + 2 * lr;
                float p0 = tf32r(__expf(s[mi][ni][0]));
                float p1 = tf32r(__expf(s[mi][ni][1]));
                float p2 = tf32r(__expf(s[mi][ni][2]));
                float p3 = tf32r(__expf(s[mi][ni][3]));
                *(float2*)(sP + r0 * LPS + col) = make_float2(p0, p1);
                *(float2*)(sP + (r0 + 8) * LPS + col) = make_float2(p2, p3);
                rs[mi][0] += p0 + p1;
                rs[mi][1] += p2 + p3;
            }
        }
#pragma unroll
        for (int mi = 0; mi < 2; mi++)
#pragma unroll
            for (int half = 0; half < 2; half++) {
                float v = rs[mi][half];
                v += __shfl_xor_sync(0xffffffffu, v, 1);
                v += __shfl_xor_sync(0xffffffffu, v, 2);
                if (lr == 0) atomicAdd(&sL[wm + mi * 16 + half * 8 + lq], v);
            }
        __syncthreads();

        // O += P[128x64] @ V[64x96]  (warp tile 32x48)
#pragma unroll
        for (int kk = 0; kk < 8; kk++) {
            int k8 = kk * 8;
            unsigned af[2][4];
#pragma unroll
            for (int mi = 0; mi < 2; mi++) {
                int r = wm + mi * 16;
                af[mi][0] = __float_as_uint(sP[(r + lq) * LPS + k8 + lr]);
                af[mi][1] = __float_as_uint(sP[(r + 8 + lq) * LPS + k8 + lr]);
                af[mi][2] = __float_as_uint(sP[(r + lq) * LPS + k8 + lr + 4]);
                af[mi][3] = __float_as_uint(sP[(r + 8 + lq) * LPS + k8 + lr + 4]);
            }
            unsigned bf[6][2];
#pragma unroll
            for (int ni = 0; ni < 6; ni++) {
                int c = wn2 * 48 + ni * 8 + lq;
                bf[ni][0] = __float_as_uint(sV[(k8 + lr) * LVS + c]);
                bf[ni][1] = __float_as_uint(sV[(k8 + lr + 4) * LVS + c]);
            }
#pragma unroll
            for (int mi = 0; mi < 2; mi++)
#pragma unroll
                for (int ni = 0; ni < 6; ni++)
                    mma8(o[mi][ni], af[mi], bf[ni]);
        }
        __syncthreads();
    }

    // normalize by row sums, write ctx[b, n, h*d + dd]
    const int b = bh >> 3, h = bh & 7;
#pragma unroll
    for (int mi = 0; mi < 2; mi++) {
        int r0 = wm + mi * 16 + lq;
        float inv0 = 1.f / sL[r0];
        float inv1 = 1.f / sL[r0 + 8];
        size_t t0 = (size_t)(b * SEQ + qb + r0) * EMB_ + h * HDIM;
        size_t t1 = (size_t)(b * SEQ + qb + r0 + 8) * EMB_ + h * HDIM;
#pragma unroll
        for (int ni = 0; ni < 6; ni++) {
            int col = wn2 * 48 + ni * 8 + 2 * lr;
            *(float2*)(g_ctx + t0 + col) =
                make_float2(o[mi][ni][0] * inv0, o[mi][ni][1] * inv0);
            *(float2*)(g_ctx + t1 + col) =
                make_float2(o[mi][ni][2] * inv1, o[mi][ni][3] * inv1);
        }
    }
}

// ---------------- launch -----------------------------------------------------
extern "C" void kernel_launch(void* const* d_in, const int* in_sizes, int n_in,
                              void* d_out, int out_size) {
    const float* x     = (const float*)d_in[0];
    const float* Wqkv  = (const float*)d_in[1];
    const float* bqkv  = (const float*)d_in[2];
    const float* Wproj = (const float*)d_in[3];
    const float* bproj = (const float*)d_in[4];
    float* out = (float*)d_out;

    void *py, *pctx;
    cudaGetSymbolAddress(&py, g_y);
    cudaGetSymbolAddress(&pctx, g_ctx);

    const int gemm_smem = (2 * (BM * LDA) + 2 * (BKT * LDB)) * 4;                 // 71680 B
    const int attn_smem = (AQ * LQS + AK * LKS + AK * LVS + AQ * LPS + AQ) * 4;   // 138752 B
    cudaFuncSetAttribute(gemm_tf32, cudaFuncAttributeMaxDynamicSharedMemorySize, gemm_smem);
    cudaFuncSetAttribute(attn_kernel, cudaFuncAttributeMaxDynamicSharedMemorySize, attn_smem);

    // 1) y = x @ Wqkv + bqkv
    gemm_tf32<<<dim3(NQKV / BN, TOK / BM), 256, gemm_smem>>>(
        x, Wqkv, bqkv, (float*)py, TOK, NQKV, EMB_);
    // 2) split/transpose to q,k,v (q pre-scaled by 1/sqrt(768))
    reshape_qkv<<<(TOK * EMB_ + 255) / 256, 256>>>();
    // 3) attention
    attn_kernel<<<dim3(SEQ / AQ, BATCH * HEADS_), 256, attn_smem>>>();
    // 4) out = ctx @ Wproj + bproj
    gemm_tf32<<<dim3(EMB_ / BN, TOK / BM), 256, gemm_smem>>>(
        (const float*)pctx, Wproj, bproj, out, TOK, EMB_, EMB_);
}

// round 8
// speedup vs baseline: 1.2795x; 1.2795x over previous
#include <cuda_runtime.h>
#include <cstdint>

// Problem constants
#define TOK    8192
#define EMB_   768
#define NQKV   2304
#define HEADS_ 8
#define HDIM   96
#define SEQ    2048
#define BATCH  4

// log2(e)/sqrt(768): folded into q so softmax is a bare ex2.approx
#define SCALE_Q 0.05205875899635608f

// ---------------- scratch (static device globals) ---------------------------
__device__ float g_xr[TOK * EMB_];        // tf32-rounded x           (25.2MB)
__device__ float g_w1[EMB_ * NQKV];       // permuted+rounded Wqkv    ( 7.1MB)
__device__ float g_b1[NQKV];              // permuted bqkv
__device__ float g_w2[EMB_ * EMB_];       // rounded Wproj            ( 2.4MB)
__device__ float g_qkv[3 * TOK * EMB_];   // q/k/v planes (b,n,h,d)   (75.5MB)
__device__ float g_ctx[TOK * EMB_];       // attention out            (25.2MB)

// ---------------- helpers ---------------------------------------------------
__device__ __forceinline__ float tf32r(float x) {
    unsigned u;
    asm("cvt.rna.tf32.f32 %0, %1;" : "=r"(u) : "f"(x));
    return __uint_as_float(u);
}
__device__ __forceinline__ float ex2f(float x) {
    float y;
    asm("ex2.approx.f32 %0, %1;" : "=f"(y) : "f"(x));
    return y;
}
__device__ __forceinline__ void cpa16(uint32_t dst, const float* src) {
    asm volatile("cp.async.cg.shared.global [%0], [%1], 16;" :: "r"(dst), "l"(src));
}
#define CP_COMMIT() asm volatile("cp.async.commit_group;")
#define CP_WAIT(n)  asm volatile("cp.async.wait_group %0;" :: "n"(n))

// D += A(16x8,row) * B(8x8,col), tf32 in / f32 acc
__device__ __forceinline__ void mma8(float c[4], const unsigned a[4], const unsigned b[2]) {
    asm volatile(
        "mma.sync.aligned.m16n8k8.row.col.f32.tf32.tf32.f32 "
        "{%0,%1,%2,%3}, {%4,%5,%6,%7}, {%8,%9}, {%0,%1,%2,%3};"
        : "+f"(c[0]), "+f"(c[1]), "+f"(c[2]), "+f"(c[3])
        : "r"(a[0]), "r"(a[1]), "r"(a[2]), "r"(a[3]), "r"(b[0]), "r"(b[1]));
}

// ---------------- prep kernels ----------------------------------------------
__global__ void round4_k(const float4* __restrict__ s, float4* __restrict__ d, int n4) {
    int i = blockIdx.x * 256 + threadIdx.x;
    if (i < n4) {
        float4 v = s[i];
        v.x = tf32r(v.x); v.y = tf32r(v.y); v.z = tf32r(v.z); v.w = tf32r(v.w);
        d[i] = v;
    }
}

// permute Wqkv cols (h d qkv) -> (qkv h d), round; also permute bias
__global__ void permw_k(const float* __restrict__ W, const float* __restrict__ bias) {
    int gid = blockIdx.x * 256 + threadIdx.x;
    if (gid < EMB_ * NQKV / 4) {
        int o4 = gid * 4;
        int k = o4 / NQKV, j = o4 - k * NQKV;
        int qkv = j / 768, hd = j - qkv * 768;
        const float* src = W + (size_t)k * NQKV + qkv;
        float4 v;
        v.x = tf32r(src[(hd + 0) * 3]);
        v.y = tf32r(src[(hd + 1) * 3]);
        v.z = tf32r(src[(hd + 2) * 3]);
        v.w = tf32r(src[(hd + 3) * 3]);
        *(float4*)(g_w1 + o4) = v;
    }
    if (gid < NQKV) {
        int qkv = gid / 768, hd = gid - qkv * 768;
        g_b1[gid] = bias[hd * 3 + qkv];
    }
}

// ---------------- tf32 GEMM, cp.async 3-stage, 128x256 block ----------------
#define BM  128
#define BN  256
#define BK  32
#define LDA 36      // 36 % 32 == 4 -> conflict-free A frags
#define LDB 264     // 264 % 32 == 8 -> conflict-free B frags
#define STG 3
#define STAGE_F (BM * LDA + BK * LDB)   // 13056 floats / stage

__device__ __forceinline__ void gemm_issue(
    uint32_t smb, const float* __restrict__ A, const float* __restrict__ W,
    int bm, int bn, int K, int N, int tid, int kt)
{
    const int k0 = kt * BK;
    const uint32_t sb = smb + (uint32_t)((kt % STG) * STAGE_F) * 4u;
#pragma unroll
    for (int i = 0; i < 4; i++) {               // A: 128 rows x 8 chunks
        int id = tid + 256 * i, r = id >> 3, c = id & 7;
        cpa16(sb + (uint32_t)(r * LDA + c * 4) * 4u,
              A + (size_t)(bm + r) * K + k0 + c * 4);
    }
    const uint32_t sbB = sb + (uint32_t)(BM * LDA) * 4u;
#pragma unroll
    for (int i = 0; i < 8; i++) {               // B: 32 rows x 64 chunks
        int id = tid + 256 * i, kr = id >> 6, c = id & 63;
        cpa16(sbB + (uint32_t)(kr * LDB + c * 4) * 4u,
              W + (size_t)(k0 + kr) * N + bn + c * 4);
    }
    CP_COMMIT();
}

__global__ __launch_bounds__(256, 1) void gemm_tf32(
    const float* __restrict__ A, const float* __restrict__ W,
    const float* __restrict__ bias, float* __restrict__ C,
    int M, int N, int K, int qkv_mode)
{
    extern __shared__ float sm[];
    const uint32_t smb = (uint32_t)__cvta_generic_to_shared(sm);

    const int bm = blockIdx.y * BM, bn = blockIdx.x * BN;
    const int tid = threadIdx.x;
    const int w = tid >> 5, lane = tid & 31, lq = lane >> 2, lr = lane & 3;
    const int wm = (w & 1) * 64, wn = (w >> 1) * 64;   // 2 m-warps x 4 n-warps, 64x64 tiles

    float acc[4][8][4];
#pragma unroll
    for (int i = 0; i < 4; i++)
#pragma unroll
        for (int j = 0; j < 8; j++)
#pragma unroll
            for (int q = 0; q < 4; q++) acc[i][j][q] = 0.f;

    gemm_issue(smb, A, W, bm, bn, K, N, tid, 0);
    gemm_issue(smb, A, W, bm, bn, K, N, tid, 1);

    const int nkt = K / BK;
    for (int kt = 0; kt < nkt; ++kt) {
        if (kt + 1 < nkt) { CP_WAIT(1); } else { CP_WAIT(0); }
        __syncthreads();
        if (kt + 2 < nkt) gemm_issue(smb, A, W, bm, bn, K, N, tid, kt + 2);

        const float* cA = sm + (kt % STG) * STAGE_F;
        const float* cB = cA + BM * LDA;

#pragma unroll
        for (int kk = 0; kk < 4; kk++) {
            const int k8 = kk * 8;
            unsigned af[4][4];
#pragma unroll
            for (int mi = 0; mi < 4; mi++) {
                int r = wm + mi * 16;
                af[mi][0] = __float_as_uint(cA[(r + lq) * LDA + k8 + lr]);
                af[mi][1] = __float_as_uint(cA[(r + 8 + lq) * LDA + k8 + lr]);
                af[mi][2] = __float_as_uint(cA[(r + lq) * LDA + k8 + lr + 4]);
                af[mi][3] = __float_as_uint(cA[(r + 8 + lq) * LDA + k8 + lr + 4]);
            }
            unsigned bf[8][2];
#pragma unroll
            for (int ni = 0; ni < 8; ni++) {
                int c = wn + ni * 8 + lq;
                bf[ni][0] = __float_as_uint(cB[(k8 + lr) * LDB + c]);
                bf[ni][1] = __float_as_uint(cB[(k8 + lr + 4) * LDB + c]);
            }
#pragma unroll
            for (int mi = 0; mi < 4; mi++)
#pragma unroll
                for (int ni = 0; ni < 8; ni++)
                    mma8(acc[mi][ni], af[mi], bf[ni]);
        }
    }

    // epilogue
    if (qkv_mode) {
        // scatter into q/k/v planes; round tf32; scale q by log2e/sqrt(768)
#pragma unroll
        for (int ni = 0; ni < 8; ni++) {
            int j = bn + wn + ni * 8 + 2 * lr;
            int qkv = j / 768, pc = j - qkv * 768;
            float sc = (qkv == 0) ? SCALE_Q : 1.f;
            float b0 = bias[j], b1 = bias[j + 1];
            float* dst = C + (size_t)qkv * TOK * EMB_;
#pragma unroll
            for (int mi = 0; mi < 4; mi++) {
                int t = bm + wm + mi * 16 + lq;
                float2 v0 = make_float2(tf32r((acc[mi][ni][0] + b0) * sc),
                                        tf32r((acc[mi][ni][1] + b1) * sc));
                float2 v1 = make_float2(tf32r((acc[mi][ni][2] + b0) * sc),
                                        tf32r((acc[mi][ni][3] + b1) * sc));
                *(float2*)(dst + (size_t)t * EMB_ + pc) = v0;
                *(float2*)(dst + (size_t)(t + 8) * EMB_ + pc) = v1;
            }
        }
    } else {
#pragma unroll
        for (int ni = 0; ni < 8; ni++) {
            int col = bn + wn + ni * 8 + 2 * lr;
            float b0 = bias[col], b1 = bias[col + 1];
#pragma unroll
            for (int mi = 0; mi < 4; mi++) {
                int r0 = bm + wm + mi * 16 + lq;
                *(float2*)(C + (size_t)r0 * N + col) =
                    make_float2(acc[mi][ni][0] + b0, acc[mi][ni][1] + b1);
                *(float2*)(C + (size_t)(r0 + 8) * N + col) =
                    make_float2(acc[mi][ni][2] + b0, acc[mi][ni][3] + b1);
            }
        }
    }
}

// ---------------- attention: cp.async double-buffered, reg row-sums ---------
#define AQ  128
#define AK  64
#define LQS 100
#define LKS 100
#define LVS 104
#define LPS 68
#define OFF_K 12800
#define OFF_V 25600
#define OFF_P 38912
#define OFF_L 47616
#define ATT_F 47744
#define NIT (SEQ / AK)

// K tile: 64 rows x 24 float4 chunks = 1536; V tile: same. 3072 chunks total
// over 256 threads = 12 iterations. (R5 bug: ran only 768 chunks.)
__device__ __forceinline__ void attn_issue(
    uint32_t smb, const float* __restrict__ Kg, const float* __restrict__ Vg,
    int tid, int it)
{
    const int base_n = it * AK;
    const int buf = it & 1;
#pragma unroll
    for (int i = 0; i < 12; i++) {
        int id = tid + 256 * i;
        if (id < 1536) {
            int r = id / 24, c = id - r * 24;
            cpa16(smb + (uint32_t)(OFF_K + buf * (AK * LKS) + r * LKS + c * 4) * 4u,
                  Kg + (size_t)(base_n + r) * EMB_ + c * 4);
        } else {
            int id2 = id - 1536;
            int r = id2 / 24, c = id2 - r * 24;
            cpa16(smb + (uint32_t)(OFF_V + buf * (AK * LVS) + r * LVS + c * 4) * 4u,
                  Vg + (size_t)(base_n + r) * EMB_ + c * 4);
        }
    }
}

__global__ __launch_bounds__(256, 1) void attn2() {
    extern __shared__ float sm[];
    const uint32_t smb = (uint32_t)__cvta_generic_to_shared(sm);
    float* sP = sm + OFF_P;
    float* sL = sm + OFF_L;

    const int bh = blockIdx.y;
    const int qb = blockIdx.x * AQ;
    const int b = bh >> 3, h = bh & 7;
    const int tid = threadIdx.x, w = tid >> 5, lane = tid & 31;
    const int lq = lane >> 2, lr = lane & 3;
    const int wm = (w & 3) * 32, wn2 = w >> 2;

    const float* Qg = g_qkv + (size_t)(b * SEQ + qb) * EMB_ + h * HDIM;
    const float* Kg = g_qkv + (size_t)TOK * EMB_ + (size_t)(b * SEQ) * EMB_ + h * HDIM;
    const float* Vg = Kg + (size_t)TOK * EMB_;

    if (tid < AQ) sL[tid] = 0.f;

    // prologue: Q tile (128 rows x 24 chunks = 3072 = 12*256) + KV stage 0
#pragma unroll
    for (int i = 0; i < 12; i++) {
        int id = tid + 256 * i;
        int r = id / 24, c = id - r * 24;
        cpa16(smb + (uint32_t)(r * LQS + c * 4) * 4u, Qg + (size_t)r * EMB_ + c * 4);
    }
    attn_issue(smb, Kg, Vg, tid, 0);
    CP_COMMIT();

    float o[2][6][4];
#pragma unroll
    for (int i = 0; i < 2; i++)
#pragma unroll
        for (int j = 0; j < 6; j++)
#pragma unroll
            for (int q = 0; q < 4; q++) o[i][j][q] = 0.f;
    float rs[2][2] = {{0.f, 0.f}, {0.f, 0.f}};

    for (int it = 0; it < NIT; ++it) {
        CP_WAIT(0);
        __syncthreads();
        if (it + 1 < NIT) { attn_issue(smb, Kg, Vg, tid, it + 1); CP_COMMIT(); }

        const float* cK = sm + OFF_K + (it & 1) * (AK * LKS);
        const float* cV = sm + OFF_V + (it & 1) * (AK * LVS);

        // S[128x64] = Q @ K^T (warp tile 32x32)
        float s[2][4][4];
#pragma unroll
        for (int i = 0; i < 2; i++)
#pragma unroll
            for (int j = 0; j < 4; j++)
#pragma unroll
                for (int q = 0; q < 4; q++) s[i][j][q] = 0.f;

#pragma unroll
        for (int kk = 0; kk < 12; kk++) {
            int k8 = kk * 8;
            unsigned af[2][4];
#pragma unroll
            for (int mi = 0; mi < 2; mi++) {
                int r = wm + mi * 16;
                af[mi][0] = __float_as_uint(sm[(r + lq) * LQS + k8 + lr]);
                af[mi][1] = __float_as_uint(sm[(r + 8 + lq) * LQS + k8 + lr]);
                af[mi][2] = __float_as_uint(sm[(r + lq) * LQS + k8 + lr + 4]);
                af[mi][3] = __float_as_uint(sm[(r + 8 + lq) * LQS + k8 + lr + 4]);
            }
            unsigned bf[4][2];
#pragma unroll
            for (int ni = 0; ni < 4; ni++) {
                int c = wn2 * 32 + ni * 8 + lq;
                bf[ni][0] = __float_as_uint(cK[c * LKS + k8 + lr]);
                bf[ni][1] = __float_as_uint(cK[c * LKS + k8 + lr + 4]);
            }
#pragma unroll
            for (int mi = 0; mi < 2; mi++)
#pragma unroll
                for (int ni = 0; ni < 4; ni++)
                    mma8(s[mi][ni], af[mi], bf[ni]);
        }

        // P = 2^S (q pre-scaled by log2e/sqrt(768)); row sums in registers
#pragma unroll
        for (int mi = 0; mi < 2; mi++) {
            int r0 = wm + mi * 16 + lq;
#pragma unroll
            for (int ni = 0; ni < 4; ni++) {
                int col = wn2 * 32 + ni * 8 + 2 * lr;
                float p0 = tf32r(ex2f(s[mi][ni][0]));
                float p1 = tf32r(ex2f(s[mi][ni][1]));
                float p2 = tf32r(ex2f(s[mi][ni][2]));
                float p3 = tf32r(ex2f(s[mi][ni][3]));
                *(float2*)(sP + r0 * LPS + col) = make_float2(p0, p1);
                *(float2*)(sP + (r0 + 8) * LPS + col) = make_float2(p2, p3);
                rs[mi][0] += p0 + p1;
                rs[mi][1] += p2 + p3;
            }
        }
        // exchange P between the two n-warps sharing these rows (w <-> w^4)
        asm volatile("bar.sync %0, 64;" :: "r"(1 + (w & 3)) : "memory");

        // O += P @ V (warp tile 32x48)
#pragma unroll
        for (int kk = 0; kk < 8; kk++) {
            int k8 = kk * 8;
            unsigned af[2][4];
#pragma unroll
            for (int mi = 0; mi < 2; mi++) {
                int r = wm + mi * 16;
                af[mi][0] = __float_as_uint(sP[(r + lq) * LPS + k8 + lr]);
                af[mi][1] = __float_as_uint(sP[(r + 8 + lq) * LPS + k8 + lr]);
                af[mi][2] = __float_as_uint(sP[(r + lq) * LPS + k8 + lr + 4]);
                af[mi][3] = __float_as_uint(sP[(r + 8 + lq) * LPS + k8 + lr + 4]);
            }
            unsigned bf[6][2];
#pragma unroll
            for (int ni = 0; ni < 6; ni++) {
                int c = wn2 * 48 + ni * 8 + lq;
                bf[ni][0] = __float_as_uint(cV[(k8 + lr) * LVS + c]);
                bf[ni][1] = __float_as_uint(cV[(k8 + lr + 4) * LVS + c]);
            }
#pragma unroll
            for (int mi = 0; mi < 2; mi++)
#pragma unroll
                for (int ni = 0; ni < 6; ni++)
                    mma8(o[mi][ni], af[mi], bf[ni]);
        }
    }

    // fold register row-sums: reduce over lr, then across the n-warp pair
#pragma unroll
    for (int mi = 0; mi < 2; mi++)
#pragma unroll
        for (int half = 0; half < 2; half++) {
            float v = rs[mi][half];
            v += __shfl_xor_sync(0xffffffffu, v, 1);
            v += __shfl_xor_sync(0xffffffffu, v, 2);
            if (lr == 0) atomicAdd(&sL[wm + mi * 16 + half * 8 + lq], v);
        }
    __syncthreads();

    // normalize + tf32-round ctx (gemm2 consumes it raw via cp.async)
#pragma unroll
    for (int mi = 0; mi < 2; mi++) {
        int r0 = wm + mi * 16 + lq;
        float inv0 = 1.f / sL[r0];
        float inv1 = 1.f / sL[r0 + 8];
        size_t t0 = (size_t)(b * SEQ + qb + r0) * EMB_ + h * HDIM;
        size_t t1 = (size_t)(b * SEQ + qb + r0 + 8) * EMB_ + h * HDIM;
#pragma unroll
        for (int ni = 0; ni < 6; ni++) {
            int col = wn2 * 48 + ni * 8 + 2 * lr;
            *(float2*)(g_ctx + t0 + col) = make_float2(tf32r(o[mi][ni][0] * inv0),
                                                       tf32r(o[mi][ni][1] * inv0));
            *(float2*)(g_ctx + t1 + col) = make_float2(tf32r(o[mi][ni][2] * inv1),
                                                       tf32r(o[mi][ni][3] * inv1));
        }
    }
}

// ---------------- launch -----------------------------------------------------
extern "C" void kernel_launch(void* const* d_in, const int* in_sizes, int n_in,
                              void* d_out, int out_size) {
    const float* x     = (const float*)d_in[0];
    const float* Wqkv  = (const float*)d_in[1];
    const float* bqkv  = (const float*)d_in[2];
    const float* Wproj = (const float*)d_in[3];
    const float* bproj = (const float*)d_in[4];
    float* out = (float*)d_out;

    void *pxr, *pw1, *pb1, *pw2, *pqkv, *pctx;
    cudaGetSymbolAddress(&pxr, g_xr);
    cudaGetSymbolAddress(&pw1, g_w1);
    cudaGetSymbolAddress(&pb1, g_b1);
    cudaGetSymbolAddress(&pw2, g_w2);
    cudaGetSymbolAddress(&pqkv, g_qkv);
    cudaGetSymbolAddress(&pctx, g_ctx);

    const int gemm_smem = STG * STAGE_F * 4;   // 156672 B
    const int attn_smem = ATT_F * 4;           // 190976 B
    cudaFuncSetAttribute(gemm_tf32, cudaFuncAttributeMaxDynamicSharedMemorySize, gemm_smem);
    cudaFuncSetAttribute(attn2, cudaFuncAttributeMaxDynamicSharedMemorySize, attn_smem);

    // 0) prep: round x / Wproj; permute+round Wqkv (+bias)
    round4_k<<<(TOK * EMB_ / 4 + 255) / 256, 256>>>((const float4*)x, (float4*)pxr, TOK * EMB_ / 4);
    round4_k<<<(EMB_ * EMB_ / 4 + 255) / 256, 256>>>((const float4*)Wproj, (float4*)pw2, EMB_ * EMB_ / 4);
    permw_k<<<(EMB_ * NQKV / 4 + 255) / 256, 256>>>(Wqkv, bqkv);

    // 1) qkv = x @ Wqkv' + bqkv'  -> q/k/v planes (fused reshape, q pre-scaled)
    gemm_tf32<<<dim3(NQKV / BN, TOK / BM), 256, gemm_smem>>>(
        (const float*)pxr, (const float*)pw1, (const float*)pb1, (float*)pqkv,
        TOK, NQKV, EMB_, 1);

    // 2) attention
    attn2<<<dim3(SEQ / AQ, BATCH * HEADS_), 256, attn_smem>>>();

    // 3) out = ctx @ Wproj + bproj
    gemm_tf32<<<dim3(EMB_ / BN, TOK / BM), 256, gemm_smem>>>(
        (const float*)pctx, (const float*)pw2, bproj, out,
        TOK, EMB_, EMB_, 0);
}

// round 9
// speedup vs baseline: 1.4267x; 1.1151x over previous
#include <cuda_runtime.h>
#include <cstdint>

// Problem constants
#define TOK    8192
#define EMB_   768
#define NQKV   2304
#define HEADS_ 8
#define HDIM   96
#define SEQ    2048
#define BATCH  4

// log2(e)/sqrt(768): folded into q so softmax is a bare ex2.approx
#define SCALE_Q 0.05205875899635608f

// ---------------- scratch (static device globals) ---------------------------
__device__ float g_xr[TOK * EMB_];        // tf32-rounded x
__device__ float g_w1[EMB_ * NQKV];       // permuted+rounded Wqkv
__device__ float g_b1[NQKV];              // permuted bqkv
__device__ float g_w2[EMB_ * EMB_];       // rounded Wproj
__device__ float g_qkv[3 * TOK * EMB_];   // q/k/v planes (b,n,h,d)
__device__ float g_ctx[TOK * EMB_];       // attention out

// ---------------- helpers ---------------------------------------------------
__device__ __forceinline__ float tf32r(float x) {
    unsigned u;
    asm("cvt.rna.tf32.f32 %0, %1;" : "=r"(u) : "f"(x));
    return __uint_as_float(u);
}
__device__ __forceinline__ float ex2f(float x) {
    float y;
    asm("ex2.approx.f32 %0, %1;" : "=f"(y) : "f"(x));
    return y;
}
__device__ __forceinline__ void cpa16(uint32_t dst, const float* src) {
    asm volatile("cp.async.cg.shared.global [%0], [%1], 16;" :: "r"(dst), "l"(src));
}
#define CP_COMMIT() asm volatile("cp.async.commit_group;")
#define CP_WAIT(n)  asm volatile("cp.async.wait_group %0;" :: "n"(n))

// D += A(16x8,row) * B(8x8,col), tf32 in / f32 acc
__device__ __forceinline__ void mma8(float c[4], const unsigned a[4], const unsigned b[2]) {
    asm volatile(
        "mma.sync.aligned.m16n8k8.row.col.f32.tf32.tf32.f32 "
        "{%0,%1,%2,%3}, {%4,%5,%6,%7}, {%8,%9}, {%0,%1,%2,%3};"
        : "+f"(c[0]), "+f"(c[1]), "+f"(c[2]), "+f"(c[3])
        : "r"(a[0]), "r"(a[1]), "r"(a[2]), "r"(a[3]), "r"(b[0]), "r"(b[1]));
}

// ---------------- prep kernels ----------------------------------------------
__global__ void round4_k(const float4* __restrict__ s, float4* __restrict__ d, int n4) {
    int i = blockIdx.x * 256 + threadIdx.x;
    if (i < n4) {
        float4 v = s[i];
        v.x = tf32r(v.x); v.y = tf32r(v.y); v.z = tf32r(v.z); v.w = tf32r(v.w);
        d[i] = v;
    }
}

// permute Wqkv cols (h d qkv) -> (qkv h d), round; also permute bias
__global__ void permw_k(const float* __restrict__ W, const float* __restrict__ bias) {
    int gid = blockIdx.x * 256 + threadIdx.x;
    if (gid < EMB_ * NQKV / 4) {
        int o4 = gid * 4;
        int k = o4 / NQKV, j = o4 - k * NQKV;
        int qkv = j / 768, hd = j - qkv * 768;
        const float* src = W + (size_t)k * NQKV + qkv;
        float4 v;
        v.x = tf32r(src[(hd + 0) * 3]);
        v.y = tf32r(src[(hd + 1) * 3]);
        v.z = tf32r(src[(hd + 2) * 3]);
        v.w = tf32r(src[(hd + 3) * 3]);
        *(float4*)(g_w1 + o4) = v;
    }
    if (gid < NQKV) {
        int qkv = gid / 768, hd = gid - qkv * 768;
        g_b1[gid] = bias[hd * 3 + qkv];
    }
}

// ---------------- tf32 GEMM, cp.async 3-stage, 128x256 block ----------------
#define BM  128
#define BN  256
#define BK  32
#define LDA 36
#define LDB 264
#define STG 3
#define STAGE_F (BM * LDA + BK * LDB)

__device__ __forceinline__ void gemm_issue(
    uint32_t smb, const float* __restrict__ A, const float* __restrict__ W,
    int bm, int bn, int K, int N, int tid, int kt)
{
    const int k0 = kt * BK;
    const uint32_t sb = smb + (uint32_t)((kt % STG) * STAGE_F) * 4u;
#pragma unroll
    for (int i = 0; i < 4; i++) {
        int id = tid + 256 * i, r = id >> 3, c = id & 7;
        cpa16(sb + (uint32_t)(r * LDA + c * 4) * 4u,
              A + (size_t)(bm + r) * K + k0 + c * 4);
    }
    const uint32_t sbB = sb + (uint32_t)(BM * LDA) * 4u;
#pragma unroll
    for (int i = 0; i < 8; i++) {
        int id = tid + 256 * i, kr = id >> 6, c = id & 63;
        cpa16(sbB + (uint32_t)(kr * LDB + c * 4) * 4u,
              W + (size_t)(k0 + kr) * N + bn + c * 4);
    }
    CP_COMMIT();
}

__global__ __launch_bounds__(256, 1) void gemm_tf32(
    const float* __restrict__ A, const float* __restrict__ W,
    const float* __restrict__ bias, float* __restrict__ C,
    int M, int N, int K, int qkv_mode)
{
    extern __shared__ float sm[];
    const uint32_t smb = (uint32_t)__cvta_generic_to_shared(sm);

    const int bm = blockIdx.y * BM, bn = blockIdx.x * BN;
    const int tid = threadIdx.x;
    const int w = tid >> 5, lane = tid & 31, lq = lane >> 2, lr = lane & 3;
    const int wm = (w & 1) * 64, wn = (w >> 1) * 64;

    float acc[4][8][4];
#pragma unroll
    for (int i = 0; i < 4; i++)
#pragma unroll
        for (int j = 0; j < 8; j++)
#pragma unroll
            for (int q = 0; q < 4; q++) acc[i][j][q] = 0.f;

    gemm_issue(smb, A, W, bm, bn, K, N, tid, 0);
    gemm_issue(smb, A, W, bm, bn, K, N, tid, 1);

    const int nkt = K / BK;
    for (int kt = 0; kt < nkt; ++kt) {
        if (kt + 1 < nkt) { CP_WAIT(1); } else { CP_WAIT(0); }
        __syncthreads();
        if (kt + 2 < nkt) gemm_issue(smb, A, W, bm, bn, K, N, tid, kt + 2);

        const float* cA = sm + (kt % STG) * STAGE_F;
        const float* cB = cA + BM * LDA;

#pragma unroll
        for (int kk = 0; kk < 4; kk++) {
            const int k8 = kk * 8;
            unsigned af[4][4];
#pragma unroll
            for (int mi = 0; mi < 4; mi++) {
                int r = wm + mi * 16;
                af[mi][0] = __float_as_uint(cA[(r + lq) * LDA + k8 + lr]);
                af[mi][1] = __float_as_uint(cA[(r + 8 + lq) * LDA + k8 + lr]);
                af[mi][2] = __float_as_uint(cA[(r + lq) * LDA + k8 + lr + 4]);
                af[mi][3] = __float_as_uint(cA[(r + 8 + lq) * LDA + k8 + lr + 4]);
            }
            unsigned bf[8][2];
#pragma unroll
            for (int ni = 0; ni < 8; ni++) {
                int c = wn + ni * 8 + lq;
                bf[ni][0] = __float_as_uint(cB[(k8 + lr) * LDB + c]);
                bf[ni][1] = __float_as_uint(cB[(k8 + lr + 4) * LDB + c]);
            }
#pragma unroll
            for (int mi = 0; mi < 4; mi++)
#pragma unroll
                for (int ni = 0; ni < 8; ni++)
                    mma8(acc[mi][ni], af[mi], bf[ni]);
        }
    }

    if (qkv_mode) {
#pragma unroll
        for (int ni = 0; ni < 8; ni++) {
            int j = bn + wn + ni * 8 + 2 * lr;
            int qkv = j / 768, pc = j - qkv * 768;
            float sc = (qkv == 0) ? SCALE_Q : 1.f;
            float b0 = bias[j], b1 = bias[j + 1];
            float* dst = C + (size_t)qkv * TOK * EMB_;
#pragma unroll
            for (int mi = 0; mi < 4; mi++) {
                int t = bm + wm + mi * 16 + lq;
                float2 v0 = make_float2(tf32r((acc[mi][ni][0] + b0) * sc),
                                        tf32r((acc[mi][ni][1] + b1) * sc));
                float2 v1 = make_float2(tf32r((acc[mi][ni][2] + b0) * sc),
                                        tf32r((acc[mi][ni][3] + b1) * sc));
                *(float2*)(dst + (size_t)t * EMB_ + pc) = v0;
                *(float2*)(dst + (size_t)(t + 8) * EMB_ + pc) = v1;
            }
        }
    } else {
#pragma unroll
        for (int ni = 0; ni < 8; ni++) {
            int col = bn + wn + ni * 8 + 2 * lr;
            float b0 = bias[col], b1 = bias[col + 1];
#pragma unroll
            for (int mi = 0; mi < 4; mi++) {
                int r0 = bm + wm + mi * 16 + lq;
                *(float2*)(C + (size_t)r0 * N + col) =
                    make_float2(acc[mi][ni][0] + b0, acc[mi][ni][1] + b1);
                *(float2*)(C + (size_t)(r0 + 8) * N + col) =
                    make_float2(acc[mi][ni][2] + b0, acc[mi][ni][3] + b1);
            }
        }
    }
}

// ---------------- attention: FA2-style, warp-private rows -------------------
// Block: 256 q rows, 8 warps, each warp owns 32 rows. P stays in registers
// (S c-frags shuffled into PV a-frags). No smem P, no atomics, 1 bar/iter.
#define AQ   256
#define AK   64
#define LQS  100    // 4*lq + lr bank pattern: conflict-free
#define LKS  100
#define LVS  104
#define OFF_K 25600                 // sQ = 256*100
#define OFF_V (OFF_K + 2 * AK * LKS)   // 25600 + 12800 = 38400
#define ATT_F (OFF_V + 2 * AK * LVS)   // 38400 + 13312 = 51712 floats (206848 B)
#define NIT (SEQ / AK)

// K tile: 64 rows x 24 float4 = 1536 chunks; V same; 3072 over 256 thr = 12.
__device__ __forceinline__ void attn_issue(
    uint32_t smb, const float* __restrict__ Kg, const float* __restrict__ Vg,
    int tid, int it)
{
    const int base_n = it * AK;
    const int buf = it & 1;
#pragma unroll
    for (int i = 0; i < 12; i++) {
        int id = tid + 256 * i;
        if (id < 1536) {
            int r = id / 24, c = id - r * 24;
            cpa16(smb + (uint32_t)(OFF_K + buf * (AK * LKS) + r * LKS + c * 4) * 4u,
                  Kg + (size_t)(base_n + r) * EMB_ + c * 4);
        } else {
            int id2 = id - 1536;
            int r = id2 / 24, c = id2 - r * 24;
            cpa16(smb + (uint32_t)(OFF_V + buf * (AK * LVS) + r * LVS + c * 4) * 4u,
                  Vg + (size_t)(base_n + r) * EMB_ + c * 4);
        }
    }
}

__global__ __launch_bounds__(256, 1) void attn3() {
    extern __shared__ float sm[];
    const uint32_t smb = (uint32_t)__cvta_generic_to_shared(sm);

    const int bh = blockIdx.y;
    const int qb = blockIdx.x * AQ;
    const int b = bh >> 3, h = bh & 7;
    const int tid = threadIdx.x, w = tid >> 5, lane = tid & 31;
    const int lq = lane >> 2, lr = lane & 3;
    const int wr = w * 32;                 // warp-private row base

    const float* Qg = g_qkv + (size_t)(b * SEQ + qb) * EMB_ + h * HDIM;
    const float* Kg = g_qkv + (size_t)TOK * EMB_ + (size_t)(b * SEQ) * EMB_ + h * HDIM;
    const float* Vg = Kg + (size_t)TOK * EMB_;

    // prologue: Q tile (256 rows x 24 chunks = 6144 = 24*256) + KV stage 0
#pragma unroll
    for (int i = 0; i < 24; i++) {
        int id = tid + 256 * i;
        int r = id / 24, c = id - r * 24;
        cpa16(smb + (uint32_t)(r * LQS + c * 4) * 4u, Qg + (size_t)r * EMB_ + c * 4);
    }
    attn_issue(smb, Kg, Vg, tid, 0);
    CP_COMMIT();

    float o[2][12][4];
#pragma unroll
    for (int i = 0; i < 2; i++)
#pragma unroll
        for (int j = 0; j < 12; j++)
#pragma unroll
            for (int q = 0; q < 4; q++) o[i][j][q] = 0.f;
    float rs[2][2] = {{0.f, 0.f}, {0.f, 0.f}};

    const unsigned src01 = (lane & 28) | (lr >> 1);   // 4*lq + lr/2
    const unsigned src23 = src01 + 2;
    const bool odd = (lr & 1);

    for (int it = 0; it < NIT; ++it) {
        CP_WAIT(0);
        __syncthreads();
        if (it + 1 < NIT) { attn_issue(smb, Kg, Vg, tid, it + 1); CP_COMMIT(); }

        const float* cK = sm + OFF_K + (it & 1) * (AK * LKS);
        const float* cV = sm + OFF_V + (it & 1) * (AK * LVS);

        // S[32x64] per warp = Q @ K^T
        float s[2][8][4];
#pragma unroll
        for (int i = 0; i < 2; i++)
#pragma unroll
            for (int j = 0; j < 8; j++)
#pragma unroll
                for (int q = 0; q < 4; q++) s[i][j][q] = 0.f;

#pragma unroll
        for (int kk = 0; kk < 12; kk++) {
            int k8 = kk * 8;
            unsigned af[2][4];
#pragma unroll
            for (int mi = 0; mi < 2; mi++) {
                int r = wr + mi * 16;
                af[mi][0] = __float_as_uint(sm[(r + lq) * LQS + k8 + lr]);
                af[mi][1] = __float_as_uint(sm[(r + 8 + lq) * LQS + k8 + lr]);
                af[mi][2] = __float_as_uint(sm[(r + lq) * LQS + k8 + lr + 4]);
                af[mi][3] = __float_as_uint(sm[(r + 8 + lq) * LQS + k8 + lr + 4]);
            }
            unsigned bf[8][2];
#pragma unroll
            for (int ni = 0; ni < 8; ni++) {
                int c = ni * 8 + lq;
                bf[ni][0] = __float_as_uint(cK[c * LKS + k8 + lr]);
                bf[ni][1] = __float_as_uint(cK[c * LKS + k8 + lr + 4]);
            }
#pragma unroll
            for (int mi = 0; mi < 2; mi++)
#pragma unroll
                for (int ni = 0; ni < 8; ni++)
                    mma8(s[mi][ni], af[mi], bf[ni]);
        }

        // P = tf32(2^S) in-place; accumulate lane-partial row sums
#pragma unroll
        for (int mi = 0; mi < 2; mi++)
#pragma unroll
            for (int ni = 0; ni < 8; ni++) {
                float p0 = tf32r(ex2f(s[mi][ni][0]));
                float p1 = tf32r(ex2f(s[mi][ni][1]));
                float p2 = tf32r(ex2f(s[mi][ni][2]));
                float p3 = tf32r(ex2f(s[mi][ni][3]));
                s[mi][ni][0] = p0; s[mi][ni][1] = p1;
                s[mi][ni][2] = p2; s[mi][ni][3] = p3;
                rs[mi][0] += p0 + p1;
                rs[mi][1] += p2 + p3;
            }

        // O += P @ V : A-frags built from S c-frags via shuffles
#pragma unroll
        for (int j = 0; j < 8; j++) {
            unsigned af[2][4];
#pragma unroll
            for (int mi = 0; mi < 2; mi++) {
                float x, y;
                x = __shfl_sync(0xffffffffu, s[mi][j][0], src01);
                y = __shfl_sync(0xffffffffu, s[mi][j][1], src01);
                af[mi][0] = __float_as_uint(odd ? y : x);
                x = __shfl_sync(0xffffffffu, s[mi][j][2], src01);
                y = __shfl_sync(0xffffffffu, s[mi][j][3], src01);
                af[mi][1] = __float_as_uint(odd ? y : x);
                x = __shfl_sync(0xffffffffu, s[mi][j][0], src23);
                y = __shfl_sync(0xffffffffu, s[mi][j][1], src23);
                af[mi][2] = __float_as_uint(odd ? y : x);
                x = __shfl_sync(0xffffffffu, s[mi][j][2], src23);
                y = __shfl_sync(0xffffffffu, s[mi][j][3], src23);
                af[mi][3] = __float_as_uint(odd ? y : x);
            }
            unsigned bf[12][2];
            const int k8 = j * 8;
#pragma unroll
            for (int ni = 0; ni < 12; ni++) {
                int c = ni * 8 + lq;
                bf[ni][0] = __float_as_uint(cV[(k8 + lr) * LVS + c]);
                bf[ni][1] = __float_as_uint(cV[(k8 + lr + 4) * LVS + c]);
            }
#pragma unroll
            for (int mi = 0; mi < 2; mi++)
#pragma unroll
                for (int ni = 0; ni < 12; ni++)
                    mma8(o[mi][ni], af[mi], bf[ni]);
        }
    }

    // final: quad-reduce row sums (cols partitioned over lr within each quad)
#pragma unroll
    for (int mi = 0; mi < 2; mi++)
#pragma unroll
        for (int half = 0; half < 2; half++) {
            float v = rs[mi][half];
            v += __shfl_xor_sync(0xffffffffu, v, 1);
            v += __shfl_xor_sync(0xffffffffu, v, 2);
            rs[mi][half] = v;
        }

    // normalize + tf32-round ctx
#pragma unroll
    for (int mi = 0; mi < 2; mi++) {
        int r0 = wr + mi * 16 + lq;
        float inv0 = 1.f / rs[mi][0];
        float inv1 = 1.f / rs[mi][1];
        size_t t0 = (size_t)(b * SEQ + qb + r0) * EMB_ + h * HDIM;
        size_t t1 = (size_t)(b * SEQ + qb + r0 + 8) * EMB_ + h * HDIM;
#pragma unroll
        for (int ni = 0; ni < 12; ni++) {
            int col = ni * 8 + 2 * lr;
            *(float2*)(g_ctx + t0 + col) = make_float2(tf32r(o[mi][ni][0] * inv0),
                                                       tf32r(o[mi][ni][1] * inv0));
            *(float2*)(g_ctx + t1 + col) = make_float2(tf32r(o[mi][ni][2] * inv1),
                                                       tf32r(o[mi][ni][3] * inv1));
        }
    }
}

// ---------------- launch -----------------------------------------------------
extern "C" void kernel_launch(void* const* d_in, const int* in_sizes, int n_in,
                              void* d_out, int out_size) {
    const float* x     = (const float*)d_in[0];
    const float* Wqkv  = (const float*)d_in[1];
    const float* bqkv  = (const float*)d_in[2];
    const float* Wproj = (const float*)d_in[3];
    const float* bproj = (const float*)d_in[4];
    float* out = (float*)d_out;

    void *pxr, *pw1, *pb1, *pw2, *pqkv, *pctx;
    cudaGetSymbolAddress(&pxr, g_xr);
    cudaGetSymbolAddress(&pw1, g_w1);
    cudaGetSymbolAddress(&pb1, g_b1);
    cudaGetSymbolAddress(&pw2, g_w2);
    cudaGetSymbolAddress(&pqkv, g_qkv);
    cudaGetSymbolAddress(&pctx, g_ctx);

    const int gemm_smem = STG * STAGE_F * 4;   // 156672 B
    const int attn_smem = ATT_F * 4;           // 206848 B
    cudaFuncSetAttribute(gemm_tf32, cudaFuncAttributeMaxDynamicSharedMemorySize, gemm_smem);
    cudaFuncSetAttribute(attn3, cudaFuncAttributeMaxDynamicSharedMemorySize, attn_smem);

    // 0) prep
    round4_k<<<(TOK * EMB_ / 4 + 255) / 256, 256>>>((const float4*)x, (float4*)pxr, TOK * EMB_ / 4);
    round4_k<<<(EMB_ * EMB_ / 4 + 255) / 256, 256>>>((const float4*)Wproj, (float4*)pw2, EMB_ * EMB_ / 4);
    permw_k<<<(EMB_ * NQKV / 4 + 255) / 256, 256>>>(Wqkv, bqkv);

    // 1) qkv = x @ Wqkv' + bqkv' -> q/k/v planes (q pre-scaled)
    gemm_tf32<<<dim3(NQKV / BN, TOK / BM), 256, gemm_smem>>>(
        (const float*)pxr, (const float*)pw1, (const float*)pb1, (float*)pqkv,
        TOK, NQKV, EMB_, 1);

    // 2) attention
    attn3<<<dim3(SEQ / AQ, BATCH * HEADS_), 256, attn_smem>>>();

    // 3) out = ctx @ Wproj + bproj
    gemm_tf32<<<dim3(EMB_ / BN, TOK / BM), 256, gemm_smem>>>(
        (const float*)pctx, (const float*)pw2, bproj, out,
        TOK, EMB_, EMB_, 0);
}

// round 10
// speedup vs baseline: 1.4546x; 1.0196x over previous
#include <cuda_runtime.h>
#include <cstdint>

// Problem constants
#define TOK    8192
#define EMB_   768
#define NQKV   2304
#define HEADS_ 8
#define HDIM   96
#define SEQ    2048
#define BATCH  4

// log2(e)/sqrt(768): folded into q so softmax is a bare ex2.approx
#define SCALE_Q 0.05205875899635608f

// ---------------- scratch (static device globals) ---------------------------
__device__ float g_xr[TOK * EMB_];        // tf32-rounded x
__device__ float g_w1[EMB_ * NQKV];       // permuted+rounded Wqkv
__device__ float g_b1[NQKV];              // permuted bqkv
__device__ float g_w2[EMB_ * EMB_];       // rounded Wproj
__device__ float g_qkv[3 * TOK * EMB_];   // q/k/v planes (b,n,h,d)
__device__ float g_ctx[TOK * EMB_];       // attention out

// ---------------- helpers ---------------------------------------------------
__device__ __forceinline__ float tf32r(float x) {
    unsigned u;
    asm("cvt.rna.tf32.f32 %0, %1;" : "=r"(u) : "f"(x));
    return __uint_as_float(u);
}
__device__ __forceinline__ float ex2f(float x) {
    float y;
    asm("ex2.approx.f32 %0, %1;" : "=f"(y) : "f"(x));
    return y;
}
__device__ __forceinline__ void cpa16(uint32_t dst, const float* src) {
    asm volatile("cp.async.cg.shared.global [%0], [%1], 16;" :: "r"(dst), "l"(src));
}
#define CP_COMMIT() asm volatile("cp.async.commit_group;")
#define CP_WAIT(n)  asm volatile("cp.async.wait_group %0;" :: "n"(n))

// D += A(16x8,row) * B(8x8,col), tf32 in / f32 acc
__device__ __forceinline__ void mma8(float c[4], const unsigned a[4], const unsigned b[2]) {
    asm volatile(
        "mma.sync.aligned.m16n8k8.row.col.f32.tf32.tf32.f32 "
        "{%0,%1,%2,%3}, {%4,%5,%6,%7}, {%8,%9}, {%0,%1,%2,%3};"
        : "+f"(c[0]), "+f"(c[1]), "+f"(c[2]), "+f"(c[3])
        : "r"(a[0]), "r"(a[1]), "r"(a[2]), "r"(a[3]), "r"(b[0]), "r"(b[1]));
}

// ---------------- prep kernels ----------------------------------------------
__global__ void round4_k(const float4* __restrict__ s, float4* __restrict__ d, int n4) {
    int i = blockIdx.x * 256 + threadIdx.x;
    if (i < n4) {
        float4 v = s[i];
        v.x = tf32r(v.x); v.y = tf32r(v.y); v.z = tf32r(v.z); v.w = tf32r(v.w);
        d[i] = v;
    }
}

// permute Wqkv cols (h d qkv) -> (qkv h d), round; also permute bias
__global__ void permw_k(const float* __restrict__ W, const float* __restrict__ bias) {
    int gid = blockIdx.x * 256 + threadIdx.x;
    if (gid < EMB_ * NQKV / 4) {
        int o4 = gid * 4;
        int k = o4 / NQKV, j = o4 - k * NQKV;
        int qkv = j / 768, hd = j - qkv * 768;
        const float* src = W + (size_t)k * NQKV + qkv;
        float4 v;
        v.x = tf32r(src[(hd + 0) * 3]);
        v.y = tf32r(src[(hd + 1) * 3]);
        v.z = tf32r(src[(hd + 2) * 3]);
        v.w = tf32r(src[(hd + 3) * 3]);
        *(float4*)(g_w1 + o4) = v;
    }
    if (gid < NQKV) {
        int qkv = gid / 768, hd = gid - qkv * 768;
        g_b1[gid] = bias[hd * 3 + qkv];
    }
}

// ------- tf32 GEMM, cp.async 3-stage, 128x128 block, 128 thr, 2 CTA/SM ------
#define BM  128
#define BN  128
#define BK  32
#define LDA 36      // 36 % 32 == 4 -> conflict-free A frags
#define LDB 136     // 136 % 32 == 8 -> conflict-free B frags
#define STG 3
#define STAGE_F (BM * LDA + BK * LDB)   // 8960 floats / stage (35840 B)

__device__ __forceinline__ void gemm_issue(
    uint32_t smb, const float* __restrict__ A, const float* __restrict__ W,
    int bm, int bn, int K, int N, int tid, int kt)
{
    const int k0 = kt * BK;
    const uint32_t sb = smb + (uint32_t)((kt % STG) * STAGE_F) * 4u;
#pragma unroll
    for (int i = 0; i < 8; i++) {               // A: 128 rows x 8 chunks = 1024
        int id = tid + 128 * i, r = id >> 3, c = id & 7;
        cpa16(sb + (uint32_t)(r * LDA + c * 4) * 4u,
              A + (size_t)(bm + r) * K + k0 + c * 4);
    }
    const uint32_t sbB = sb + (uint32_t)(BM * LDA) * 4u;
#pragma unroll
    for (int i = 0; i < 8; i++) {               // B: 32 rows x 32 chunks = 1024
        int id = tid + 128 * i, kr = id >> 5, c = id & 31;
        cpa16(sbB + (uint32_t)(kr * LDB + c * 4) * 4u,
              W + (size_t)(k0 + kr) * N + bn + c * 4);
    }
    CP_COMMIT();
}

__global__ __launch_bounds__(128, 2) void gemm_tf32(
    const float* __restrict__ A, const float* __restrict__ W,
    const float* __restrict__ bias, float* __restrict__ C,
    int M, int N, int K, int qkv_mode)
{
    extern __shared__ float sm[];
    const uint32_t smb = (uint32_t)__cvta_generic_to_shared(sm);

    const int bm = blockIdx.y * BM, bn = blockIdx.x * BN;
    const int tid = threadIdx.x;
    const int w = tid >> 5, lane = tid & 31, lq = lane >> 2, lr = lane & 3;
    const int wm = (w & 1) * 64, wn = (w >> 1) * 64;   // 2x2 warps, 64x64 tiles

    float acc[4][8][4];
#pragma unroll
    for (int i = 0; i < 4; i++)
#pragma unroll
        for (int j = 0; j < 8; j++)
#pragma unroll
            for (int q = 0; q < 4; q++) acc[i][j][q] = 0.f;

    gemm_issue(smb, A, W, bm, bn, K, N, tid, 0);
    gemm_issue(smb, A, W, bm, bn, K, N, tid, 1);

    const int nkt = K / BK;
    for (int kt = 0; kt < nkt; ++kt) {
        if (kt + 1 < nkt) { CP_WAIT(1); } else { CP_WAIT(0); }
        __syncthreads();
        if (kt + 2 < nkt) gemm_issue(smb, A, W, bm, bn, K, N, tid, kt + 2);

        const float* cA = sm + (kt % STG) * STAGE_F;
        const float* cB = cA + BM * LDA;

#pragma unroll
        for (int kk = 0; kk < 4; kk++) {
            const int k8 = kk * 8;
            unsigned af[4][4];
#pragma unroll
            for (int mi = 0; mi < 4; mi++) {
                int r = wm + mi * 16;
                af[mi][0] = __float_as_uint(cA[(r + lq) * LDA + k8 + lr]);
                af[mi][1] = __float_as_uint(cA[(r + 8 + lq) * LDA + k8 + lr]);
                af[mi][2] = __float_as_uint(cA[(r + lq) * LDA + k8 + lr + 4]);
                af[mi][3] = __float_as_uint(cA[(r + 8 + lq) * LDA + k8 + lr + 4]);
            }
            unsigned bf[8][2];
#pragma unroll
            for (int ni = 0; ni < 8; ni++) {
                int c = wn + ni * 8 + lq;
                bf[ni][0] = __float_as_uint(cB[(k8 + lr) * LDB + c]);
                bf[ni][1] = __float_as_uint(cB[(k8 + lr + 4) * LDB + c]);
            }
#pragma unroll
            for (int mi = 0; mi < 4; mi++)
#pragma unroll
                for (int ni = 0; ni < 8; ni++)
                    mma8(acc[mi][ni], af[mi], bf[ni]);
        }
    }

    if (qkv_mode) {
        // scatter into q/k/v planes; round tf32; scale q by log2e/sqrt(768)
#pragma unroll
        for (int ni = 0; ni < 8; ni++) {
            int j = bn + wn + ni * 8 + 2 * lr;
            int qkv = j / 768, pc = j - qkv * 768;
            float sc = (qkv == 0) ? SCALE_Q : 1.f;
            float b0 = bias[j], b1 = bias[j + 1];
            float* dst = C + (size_t)qkv * TOK * EMB_;
#pragma unroll
            for (int mi = 0; mi < 4; mi++) {
                int t = bm + wm + mi * 16 + lq;
                float2 v0 = make_float2(tf32r((acc[mi][ni][0] + b0) * sc),
                                        tf32r((acc[mi][ni][1] + b1) * sc));
                float2 v1 = make_float2(tf32r((acc[mi][ni][2] + b0) * sc),
                                        tf32r((acc[mi][ni][3] + b1) * sc));
                *(float2*)(dst + (size_t)t * EMB_ + pc) = v0;
                *(float2*)(dst + (size_t)(t + 8) * EMB_ + pc) = v1;
            }
        }
    } else {
#pragma unroll
        for (int ni = 0; ni < 8; ni++) {
            int col = bn + wn + ni * 8 + 2 * lr;
            float b0 = bias[col], b1 = bias[col + 1];
#pragma unroll
            for (int mi = 0; mi < 4; mi++) {
                int r0 = bm + wm + mi * 16 + lq;
                *(float2*)(C + (size_t)r0 * N + col) =
                    make_float2(acc[mi][ni][0] + b0, acc[mi][ni][1] + b1);
                *(float2*)(C + (size_t)(r0 + 8) * N + col) =
                    make_float2(acc[mi][ni][2] + b0, acc[mi][ni][3] + b1);
            }
        }
    }
}

// -------- attention: FA2-style, warp-private rows, 128 thr, 2 CTA/SM --------
// Block: 128 q rows, 4 warps x 32 private rows. KV tiles AK=32, double-buffered.
#define AQ   128
#define AK   32
#define LQS  100
#define LKS  100
#define LVS  104
#define OFF_K 12800                       // sQ = 128*100
#define OFF_V (OFF_K + 2 * AK * LKS)      // 12800 + 6400  = 19200
#define ATT_F (OFF_V + 2 * AK * LVS)      // 19200 + 6656  = 25856 fl (103424 B)
#define NIT (SEQ / AK)                    // 64

// K tile: 32 rows x 24 float4 = 768 chunks; V same; 1536 over 128 thr = 12.
__device__ __forceinline__ void attn_issue(
    uint32_t smb, const float* __restrict__ Kg, const float* __restrict__ Vg,
    int tid, int it)
{
    const int base_n = it * AK;
    const int buf = it & 1;
#pragma unroll
    for (int i = 0; i < 12; i++) {
        int id = tid + 128 * i;
        if (id < 768) {
            int r = id / 24, c = id - r * 24;
            cpa16(smb + (uint32_t)(OFF_K + buf * (AK * LKS) + r * LKS + c * 4) * 4u,
                  Kg + (size_t)(base_n + r) * EMB_ + c * 4);
        } else {
            int id2 = id - 768;
            int r = id2 / 24, c = id2 - r * 24;
            cpa16(smb + (uint32_t)(OFF_V + buf * (AK * LVS) + r * LVS + c * 4) * 4u,
                  Vg + (size_t)(base_n + r) * EMB_ + c * 4);
        }
    }
}

__global__ __launch_bounds__(128, 2) void attn3() {
    extern __shared__ float sm[];
    const uint32_t smb = (uint32_t)__cvta_generic_to_shared(sm);

    const int bh = blockIdx.y;
    const int qb = blockIdx.x * AQ;
    const int b = bh >> 3, h = bh & 7;
    const int tid = threadIdx.x, w = tid >> 5, lane = tid & 31;
    const int lq = lane >> 2, lr = lane & 3;
    const int wr = w * 32;                 // warp-private row base

    const float* Qg = g_qkv + (size_t)(b * SEQ + qb) * EMB_ + h * HDIM;
    const float* Kg = g_qkv + (size_t)TOK * EMB_ + (size_t)(b * SEQ) * EMB_ + h * HDIM;
    const float* Vg = Kg + (size_t)TOK * EMB_;

    // prologue: Q tile (128 rows x 24 chunks = 3072 = 24*128) + KV stage 0
#pragma unroll
    for (int i = 0; i < 24; i++) {
        int id = tid + 128 * i;
        int r = id / 24, c = id - r * 24;
        cpa16(smb + (uint32_t)(r * LQS + c * 4) * 4u, Qg + (size_t)r * EMB_ + c * 4);
    }
    attn_issue(smb, Kg, Vg, tid, 0);
    CP_COMMIT();

    float o[2][12][4];
#pragma unroll
    for (int i = 0; i < 2; i++)
#pragma unroll
        for (int j = 0; j < 12; j++)
#pragma unroll
            for (int q = 0; q < 4; q++) o[i][j][q] = 0.f;
    float rs[2][2] = {{0.f, 0.f}, {0.f, 0.f}};

    const unsigned src01 = (lane & 28) | (lr >> 1);   // 4*lq + lr/2
    const unsigned src23 = src01 + 2;
    const bool odd = (lr & 1);

    for (int it = 0; it < NIT; ++it) {
        CP_WAIT(0);
        __syncthreads();
        if (it + 1 < NIT) { attn_issue(smb, Kg, Vg, tid, it + 1); CP_COMMIT(); }

        const float* cK = sm + OFF_K + (it & 1) * (AK * LKS);
        const float* cV = sm + OFF_V + (it & 1) * (AK * LVS);

        // S[32x32] per warp = Q @ K^T
        float s[2][4][4];
#pragma unroll
        for (int i = 0; i < 2; i++)
#pragma unroll
            for (int j = 0; j < 4; j++)
#pragma unroll
                for (int q = 0; q < 4; q++) s[i][j][q] = 0.f;

#pragma unroll
        for (int kk = 0; kk < 12; kk++) {
            int k8 = kk * 8;
            unsigned af[2][4];
#pragma unroll
            for (int mi = 0; mi < 2; mi++) {
                int r = wr + mi * 16;
                af[mi][0] = __float_as_uint(sm[(r + lq) * LQS + k8 + lr]);
                af[mi][1] = __float_as_uint(sm[(r + 8 + lq) * LQS + k8 + lr]);
                af[mi][2] = __float_as_uint(sm[(r + lq) * LQS + k8 + lr + 4]);
                af[mi][3] = __float_as_uint(sm[(r + 8 + lq) * LQS + k8 + lr + 4]);
            }
            unsigned bf[4][2];
#pragma unroll
            for (int ni = 0; ni < 4; ni++) {
                int c = ni * 8 + lq;
                bf[ni][0] = __float_as_uint(cK[c * LKS + k8 + lr]);
                bf[ni][1] = __float_as_uint(cK[c * LKS + k8 + lr + 4]);
            }
#pragma unroll
            for (int mi = 0; mi < 2; mi++)
#pragma unroll
                for (int ni = 0; ni < 4; ni++)
                    mma8(s[mi][ni], af[mi], bf[ni]);
        }

        // P = tf32(2^S) in-place; accumulate lane-partial row sums
#pragma unroll
        for (int mi = 0; mi < 2; mi++)
#pragma unroll
            for (int ni = 0; ni < 4; ni++) {
                float p0 = tf32r(ex2f(s[mi][ni][0]));
                float p1 = tf32r(ex2f(s[mi][ni][1]));
                float p2 = tf32r(ex2f(s[mi][ni][2]));
                float p3 = tf32r(ex2f(s[mi][ni][3]));
                s[mi][ni][0] = p0; s[mi][ni][1] = p1;
                s[mi][ni][2] = p2; s[mi][ni][3] = p3;
                rs[mi][0] += p0 + p1;
                rs[mi][1] += p2 + p3;
            }

        // O += P @ V : A-frags built from S c-frags via shuffles
#pragma unroll
        for (int j = 0; j < 4; j++) {
            unsigned af[2][4];
#pragma unroll
            for (int mi = 0; mi < 2; mi++) {
                float x, y;
                x = __shfl_sync(0xffffffffu, s[mi][j][0], src01);
                y = __shfl_sync(0xffffffffu, s[mi][j][1], src01);
                af[mi][0] = __float_as_uint(odd ? y : x);
                x = __shfl_sync(0xffffffffu, s[mi][j][2], src01);
                y = __shfl_sync(0xffffffffu, s[mi][j][3], src01);
                af[mi][1] = __float_as_uint(odd ? y : x);
                x = __shfl_sync(0xffffffffu, s[mi][j][0], src23);
                y = __shfl_sync(0xffffffffu, s[mi][j][1], src23);
                af[mi][2] = __float_as_uint(odd ? y : x);
                x = __shfl_sync(0xffffffffu, s[mi][j][2], src23);
                y = __shfl_sync(0xffffffffu, s[mi][j][3], src23);
                af[mi][3] = __float_as_uint(odd ? y : x);
            }
            unsigned bf[12][2];
            const int k8 = j * 8;
#pragma unroll
            for (int ni = 0; ni < 12; ni++) {
                int c = ni * 8 + lq;
                bf[ni][0] = __float_as_uint(cV[(k8 + lr) * LVS + c]);
                bf[ni][1] = __float_as_uint(cV[(k8 + lr + 4) * LVS + c]);
            }
#pragma unroll
            for (int mi = 0; mi < 2; mi++)
#pragma unroll
                for (int ni = 0; ni < 12; ni++)
                    mma8(o[mi][ni], af[mi], bf[ni]);
        }
    }

    // final: quad-reduce row sums (cols partitioned over lr within each quad)
#pragma unroll
    for (int mi = 0; mi < 2; mi++)
#pragma unroll
        for (int half = 0; half < 2; half++) {
            float v = rs[mi][half];
            v += __shfl_xor_sync(0xffffffffu, v, 1);
            v += __shfl_xor_sync(0xffffffffu, v, 2);
            rs[mi][half] = v;
        }

    // normalize + tf32-round ctx
#pragma unroll
    for (int mi = 0; mi < 2; mi++) {
        int r0 = wr + mi * 16 + lq;
        float inv0 = 1.f / rs[mi][0];
        float inv1 = 1.f / rs[mi][1];
        size_t t0 = (size_t)(b * SEQ + qb + r0) * EMB_ + h * HDIM;
        size_t t1 = (size_t)(b * SEQ + qb + r0 + 8) * EMB_ + h * HDIM;
#pragma unroll
        for (int ni = 0; ni < 12; ni++) {
            int col = ni * 8 + 2 * lr;
            *(float2*)(g_ctx + t0 + col) = make_float2(tf32r(o[mi][ni][0] * inv0),
                                                       tf32r(o[mi][ni][1] * inv0));
            *(float2*)(g_ctx + t1 + col) = make_float2(tf32r(o[mi][ni][2] * inv1),
                                                       tf32r(o[mi][ni][3] * inv1));
        }
    }
}

// ---------------- launch -----------------------------------------------------
extern "C" void kernel_launch(void* const* d_in, const int* in_sizes, int n_in,
                              void* d_out, int out_size) {
    const float* x     = (const float*)d_in[0];
    const float* Wqkv  = (const float*)d_in[1];
    const float* bqkv  = (const float*)d_in[2];
    const float* Wproj = (const float*)d_in[3];
    const float* bproj = (const float*)d_in[4];
    float* out = (float*)d_out;

    void *pxr, *pw1, *pb1, *pw2, *pqkv, *pctx;
    cudaGetSymbolAddress(&pxr, g_xr);
    cudaGetSymbolAddress(&pw1, g_w1);
    cudaGetSymbolAddress(&pb1, g_b1);
    cudaGetSymbolAddress(&pw2, g_w2);
    cudaGetSymbolAddress(&pqkv, g_qkv);
    cudaGetSymbolAddress(&pctx, g_ctx);

    const int gemm_smem = STG * STAGE_F * 4;   // 107520 B -> 2 CTAs/SM
    const int attn_smem = ATT_F * 4;           // 103424 B -> 2 CTAs/SM
    cudaFuncSetAttribute(gemm_tf32, cudaFuncAttributeMaxDynamicSharedMemorySize, gemm_smem);
    cudaFuncSetAttribute(attn3, cudaFuncAttributeMaxDynamicSharedMemorySize, attn_smem);

    // 0) prep
    round4_k<<<(TOK * EMB_ / 4 + 255) / 256, 256>>>((const float4*)x, (float4*)pxr, TOK * EMB_ / 4);
    round4_k<<<(EMB_ * EMB_ / 4 + 255) / 256, 256>>>((const float4*)Wproj, (float4*)pw2, EMB_ * EMB_ / 4);
    permw_k<<<(EMB_ * NQKV / 4 + 255) / 256, 256>>>(Wqkv, bqkv);

    // 1) qkv = x @ Wqkv' + bqkv' -> q/k/v planes (q pre-scaled)
    gemm_tf32<<<dim3(NQKV / BN, TOK / BM), 128, gemm_smem>>>(
        (const float*)pxr, (const float*)pw1, (const float*)pb1, (float*)pqkv,
        TOK, NQKV, EMB_, 1);

    // 2) attention
    attn3<<<dim3(SEQ / AQ, BATCH * HEADS_), 128, attn_smem>>>();

    // 3) out = ctx @ Wproj + bproj
    gemm_tf32<<<dim3(EMB_ / BN, TOK / BM), 128, gemm_smem>>>(
        (const float*)pctx, (const float*)pw2, bproj, out,
        TOK, EMB_, EMB_, 0);
}